// round 12
// baseline (speedup 1.0000x reference)
#include <cuda_runtime.h>

#define HH 512
#define WW 512
#define TPB 128           // 4 warps per block; each WARP owns full 512-col rows
#define NBLK 608          // 152 SMs * 4 blocks/SM (one wave at the reg-limited cap)
#define EPS 1e-6f

// scratch for per-block partial sums + completion ticket (no cudaMalloc allowed)
__device__ float g_partials[NBLK];
__device__ unsigned int g_ticket;   // zero-init; last block resets it to 0

__device__ __forceinline__ float4 ld4(const float* __restrict__ p) {
    return *reinterpret_cast<const float4*>(p);
}

// single-MUFU approximate sqrt (max rel err ~1e-7, far below 1e-3 tolerance)
__device__ __forceinline__ float fsqrt_ap(float x) {
    float r;
    asm("sqrt.approx.f32 %0, %1;" : "=f"(r) : "f"(x));
    return r;
}

__global__ __launch_bounds__(TPB, 4)   // up to 128 regs; 4 blocks/SM
void grad_loss_kernel(const float* __restrict__ in, const float* __restrict__ tg,
                      float* __restrict__ out, int total_rows, float inv_n) {
    const int t     = threadIdx.x;
    const int lane  = t & 31;
    const int wid   = t >> 5;
    const int gw    = blockIdx.x * 4 + wid;       // global warp id
    const int laneL = (lane + 31) & 31;           // rotate: lane reads lane-1 (wrap)
    const int laneR = (lane + 1) & 31;            // rotate: lane reads lane+1 (wrap)

    // contiguous row slice per warp over the flattened row space
    const int nw   = NBLK * 4;
    const int base = total_rows / nw;
    const int rem  = total_rows % nw;
    const int ws   = gw * base + min(gw, rem);
    const int we   = ws + base + (gw < rem ? 1 : 0);

    // lane covers cols {k*128 + lane*4 .. +4}, k=0..3 (512B coalesced chunk loads)
    const float* pi = in + (size_t)ws * WW + lane * 4;
    const float* pt = tg + (size_t)ws * WW + lane * 4;

    const float4 z4 = make_float4(0.f, 0.f, 0.f, 0.f);
    float sum = 0.f;

    // 3 rotating row buffers per array: roles (u=rg-1, c=rg, n=rg+1).
    // INVARIANT: the n slot always holds the TRUE row rg+1 (loaded one full
    // step earlier as a prefetch into the then-dead u slot).
    float4 Ai[4], Bi[4], Ci[4], At[4], Bt[4], Ct[4];

    #pragma unroll
    for (int k = 0; k < 4; ++k) {
        Ai[k] = (ws > 0) ? ld4(pi - WW + k * 128) : z4;                // row ws-1
        At[k] = (ws > 0) ? ld4(pt - WW + k * 128) : z4;
        Bi[k] = ld4(pi + k * 128);                                     // row ws
        Bt[k] = ld4(pt + k * 128);
        Ci[k] = (ws + 1 < total_rows) ? ld4(pi + WW + k * 128) : z4;   // row ws+1
        Ct[k] = (ws + 1 < total_rows) ? ld4(pt + WW + k * 128) : z4;
    }

    // compute row rg from (u,c,n); after chunk k's math, u[k] is DEAD -> load
    // row rg+2 chunk k into it (prefetch, consumed one full step later)
    auto rowmath = [&](float4 (&u_i)[4], float4 (&c_i)[4], const float4 (&n_i)[4],
                       float4 (&u_t)[4], float4 (&c_t)[4], const float4 (&n_t)[4],
                       bool pf) {
        #pragma unroll
        for (int k = 0; k < 4; ++k) {
            // horizontal neighbors: rotate-shuffles, register-sourced, no loads
            float xl_i = (lane == 31) ? (k > 0 ? c_i[k - 1].w : 0.f) : c_i[k].w;
            float xl_t = (lane == 31) ? (k > 0 ? c_t[k - 1].w : 0.f) : c_t[k].w;
            const float lci = __shfl_sync(0xffffffffu, xl_i, laneL);
            const float lct = __shfl_sync(0xffffffffu, xl_t, laneL);
            float xr_i = (lane == 0) ? (k < 3 ? c_i[k + 1].x : 0.f) : c_i[k].x;
            float xr_t = (lane == 0) ? (k < 3 ? c_t[k + 1].x : 0.f) : c_t[k].x;
            const float rci = __shfl_sync(0xffffffffu, xr_i, laneR);
            const float rct = __shfl_sync(0xffffffffu, xr_t, laneR);

            float gv, gh, a, b;

            gv = n_i[k].x - u_i[k].x; gh = c_i[k].y - lci;
            a  = fsqrt_ap(fmaf(gv, gv, fmaf(gh, gh, EPS)));
            gv = n_t[k].x - u_t[k].x; gh = c_t[k].y - lct;
            b  = fsqrt_ap(fmaf(gv, gv, fmaf(gh, gh, EPS)));
            sum += fabsf(a - b);

            gv = n_i[k].y - u_i[k].y; gh = c_i[k].z - c_i[k].x;
            a  = fsqrt_ap(fmaf(gv, gv, fmaf(gh, gh, EPS)));
            gv = n_t[k].y - u_t[k].y; gh = c_t[k].z - c_t[k].x;
            b  = fsqrt_ap(fmaf(gv, gv, fmaf(gh, gh, EPS)));
            sum += fabsf(a - b);

            gv = n_i[k].z - u_i[k].z; gh = c_i[k].w - c_i[k].y;
            a  = fsqrt_ap(fmaf(gv, gv, fmaf(gh, gh, EPS)));
            gv = n_t[k].z - u_t[k].z; gh = c_t[k].w - c_t[k].y;
            b  = fsqrt_ap(fmaf(gv, gv, fmaf(gh, gh, EPS)));
            sum += fabsf(a - b);

            gv = n_i[k].w - u_i[k].w; gh = rci - c_i[k].z;
            a  = fsqrt_ap(fmaf(gv, gv, fmaf(gh, gh, EPS)));
            gv = n_t[k].w - u_t[k].w; gh = rct - c_t[k].z;
            b  = fsqrt_ap(fmaf(gv, gv, fmaf(gh, gh, EPS)));
            sum += fabsf(a - b);

            // prefetch row rg+2 chunk k into the now-dead u slot
            u_i[k] = pf ? ld4(pi + 2 * WW + k * 128) : z4;
            u_t[k] = pf ? ld4(pt + 2 * WW + k * 128) : z4;
        }
    };

    // step: warp-uniform plane-edge branches, no per-pixel masks
    auto step = [&](float4 (&A_i)[4], float4 (&B_i)[4], float4 (&C_i)[4],
                    float4 (&A_t)[4], float4 (&B_t)[4], float4 (&C_t)[4], int rg) {
        const int r = rg & (HH - 1);
        const bool pf = (rg + 2 < total_rows);
        if (r == 0) {                          // plane-first: zero-pad above (slot dead)
            #pragma unroll
            for (int k = 0; k < 4; ++k) { A_i[k] = z4; A_t[k] = z4; }
        }
        if (r != HH - 1) {
            rowmath(A_i, B_i, C_i, A_t, B_t, C_t, pf);
        } else {                               // plane-last: zero-pad below for compute;
            const float4 zn[4] = {z4, z4, z4, z4};   // C keeps the real row rg+1
            rowmath(A_i, B_i, zn, A_t, B_t, zn, pf);
        }
        pi += WW; pt += WW;
    };

    int rg = ws;
    for (; rg + 3 <= we; rg += 3) {
        step(Ai, Bi, Ci, At, Bt, Ct, rg);
        step(Bi, Ci, Ai, Bt, Ct, At, rg + 1);
        step(Ci, Ai, Bi, Ct, At, Bt, rg + 2);
    }
    if (rg < we) { step(Ai, Bi, Ci, At, Bt, Ct, rg); ++rg; }
    if (rg < we) { step(Bi, Ci, Ai, Bt, Ct, At, rg); ++rg; }

    // ---------- block reduction + last-block-ticket finisher ----------
    #pragma unroll
    for (int o = 16; o > 0; o >>= 1)
        sum += __shfl_down_sync(0xffffffffu, sum, o);

    __shared__ float wsum[TPB / 32];
    __shared__ bool is_last;
    if (lane == 0) wsum[wid] = sum;
    __syncthreads();

    if (t == 0) {
        float s = wsum[0] + wsum[1] + wsum[2] + wsum[3];
        g_partials[blockIdx.x] = s;
        __threadfence();                               // partial visible before ticket
        unsigned done = atomicAdd(&g_ticket, 1u);
        is_last = (done == (unsigned)(NBLK - 1));
    }
    __syncthreads();

    if (is_last) {
        const volatile float* vp = (const volatile float*)g_partials;
        float s = 0.f;
        for (int i = t; i < NBLK; i += TPB)
            s += vp[i];

        #pragma unroll
        for (int o = 16; o > 0; o >>= 1)
            s += __shfl_down_sync(0xffffffffu, s, o);

        if (lane == 0) wsum[wid] = s;
        __syncthreads();
        if (t == 0) {
            out[0] = (wsum[0] + wsum[1] + wsum[2] + wsum[3]) * inv_n;
            g_ticket = 0;                              // reset for next graph replay
        }
    }
}

extern "C" void kernel_launch(void* const* d_in, const int* in_sizes, int n_in,
                              void* d_out, int out_size) {
    const float* in = (const float*)d_in[0];
    const float* tg = (const float*)d_in[1];
    float* out = (float*)d_out;

    const int total = in_sizes[0];                 // 32*3*512*512
    const int total_rows = total / WW;             // 49152

    grad_loss_kernel<<<NBLK, TPB>>>(in, tg, out, total_rows, 1.0f / (float)total);
}

// round 13
// speedup vs baseline: 1.1304x; 1.1304x over previous
#include <cuda_runtime.h>

#define HH 512
#define WW 512
#define TPB 128           // 4 warps per block; each WARP owns half-rows (256 cols)
#define BPSM 6
#define NBLK (152 * BPSM) // 912 blocks = one full wave at the reg-limited cap
#define EPS 1e-6f

// scratch for per-block partial sums + completion ticket (no cudaMalloc allowed)
__device__ float g_partials[NBLK];
__device__ unsigned int g_ticket;   // zero-init; last block resets it to 0

__device__ __forceinline__ float4 ld4(const float* __restrict__ p) {
    return *reinterpret_cast<const float4*>(p);
}

// single-MUFU approximate sqrt (max rel err ~1e-7, far below 1e-3 tolerance)
__device__ __forceinline__ float fsqrt_ap(float x) {
    float r;
    asm("sqrt.approx.f32 %0, %1;" : "=f"(r) : "f"(x));
    return r;
}

__global__ __launch_bounds__(TPB, BPSM)   // <=85 regs; 6 blocks/SM (37.5% occ)
void grad_loss_kernel(const float* __restrict__ in, const float* __restrict__ tg,
                      float* __restrict__ out, int total_rows, float inv_n) {
    const int t     = threadIdx.x;
    const int lane  = t & 31;
    const int wid   = t >> 5;
    const int gw    = blockIdx.x * 4 + wid;   // global warp id
    const int half  = gw & 1;                 // 0: cols [0,256), 1: cols [256,512)
    const int s     = gw >> 1;                // row-slice id
    const int laneL = (lane + 31) & 31;
    const int laneR = (lane + 1) & 31;

    // contiguous row slice per warp-pair over the flattened row space
    const int nsl  = NBLK * 2;                // 1824 slices
    const int base = total_rows / nsl;
    const int rem  = total_rows % nsl;
    const int ws   = s * base + min(s, rem);
    const int we   = ws + base + (s < rem ? 1 : 0);

    // chunk k covers cols [half*256 + k*128, +128): dense 512B warp loads
    const float* pi = in + (size_t)ws * WW + half * 256 + lane * 4;
    const float* pt = tg + (size_t)ws * WW + half * 256 + lane * 4;
    // boundary column owned by the partner warp (col 255 or 256)
    const int   ec   = half ? 255 : 256;
    const int   eln  = half ? 31 : 0;         // lane whose register feeds the shuffle
    const float* pe_i = in + (size_t)ws * WW + ec;
    const float* pe_t = tg + (size_t)ws * WW + ec;

    const float4 z4 = make_float4(0.f, 0.f, 0.f, 0.f);
    float sum = 0.f;

    // 3 rotating row buffers (u, c, n) x 2 chunks x 2 arrays, plus rotating
    // boundary scalars (edge of the row currently in the matching slot)
    float4 Ai[2], Bi[2], Ci[2], At[2], Bt[2], Ct[2];
    float eAi = 0.f, eBi = 0.f, eCi = 0.f, eAt = 0.f, eBt = 0.f, eCt = 0.f;

    #pragma unroll
    for (int k = 0; k < 2; ++k) {
        Ai[k] = (ws > 0) ? ld4(pi - WW + k * 128) : z4;   // row ws-1
        At[k] = (ws > 0) ? ld4(pt - WW + k * 128) : z4;
        Bi[k] = ld4(pi + k * 128);                        // row ws
        Bt[k] = ld4(pt + k * 128);
    }
    if (lane == eln) { eBi = pe_i[0]; eBt = pe_t[0]; }    // edge of row ws

    // step for row rg: load row rg+1 (+its edge) into the n slot, compute row
    // rg from (u, c, n). Plane-last handled by FREE fma multiplier m.
    auto step = [&](float4 (&u_i)[2], float4 (&c_i)[2], float4 (&n_i)[2],
                    float4 (&u_t)[2], float4 (&c_t)[2], float4 (&n_t)[2],
                    float& eu_i, float& ec_i, float& en_i,
                    float& eu_t, float& ec_t, float& en_t, int rg) {
        const int r = rg & (HH - 1);
        if (rg + 1 < total_rows) {
            #pragma unroll
            for (int k = 0; k < 2; ++k) {
                n_i[k] = ld4(pi + WW + k * 128);
                n_t[k] = ld4(pt + WW + k * 128);
            }
            if (lane == eln) { en_i = pe_i[WW]; en_t = pe_t[WW]; }
        } else {
            n_i[0] = z4; n_i[1] = z4; n_t[0] = z4; n_t[1] = z4;
        }
        if (r == 0) {                          // plane-first: zero-pad above (slot dead)
            u_i[0] = z4; u_i[1] = z4; u_t[0] = z4; u_t[1] = z4;
        }
        const float m = (r == HH - 1) ? 0.f : 1.f;   // plane-last: n masked in the fma

        #pragma unroll
        for (int k = 0; k < 2; ++k) {
            // horizontal neighbors: rotate-shuffles; boundary col from the
            // rotating edge scalar (loaded one row ahead, never a hot load)
            float xl_i = (lane == 31) ? (k > 0 ? c_i[0].w : (half ? ec_i : 0.f)) : c_i[k].w;
            float xl_t = (lane == 31) ? (k > 0 ? c_t[0].w : (half ? ec_t : 0.f)) : c_t[k].w;
            const float lci = __shfl_sync(0xffffffffu, xl_i, laneL);
            const float lct = __shfl_sync(0xffffffffu, xl_t, laneL);
            float xr_i = (lane == 0) ? (k < 1 ? c_i[1].x : (half ? 0.f : ec_i)) : c_i[k].x;
            float xr_t = (lane == 0) ? (k < 1 ? c_t[1].x : (half ? 0.f : ec_t)) : c_t[k].x;
            const float rci = __shfl_sync(0xffffffffu, xr_i, laneR);
            const float rct = __shfl_sync(0xffffffffu, xr_t, laneR);

            float gv, gh, a, b;

            gv = fmaf(n_i[k].x, m, -u_i[k].x); gh = c_i[k].y - lci;
            a  = fsqrt_ap(fmaf(gv, gv, fmaf(gh, gh, EPS)));
            gv = fmaf(n_t[k].x, m, -u_t[k].x); gh = c_t[k].y - lct;
            b  = fsqrt_ap(fmaf(gv, gv, fmaf(gh, gh, EPS)));
            sum += fabsf(a - b);

            gv = fmaf(n_i[k].y, m, -u_i[k].y); gh = c_i[k].z - c_i[k].x;
            a  = fsqrt_ap(fmaf(gv, gv, fmaf(gh, gh, EPS)));
            gv = fmaf(n_t[k].y, m, -u_t[k].y); gh = c_t[k].z - c_t[k].x;
            b  = fsqrt_ap(fmaf(gv, gv, fmaf(gh, gh, EPS)));
            sum += fabsf(a - b);

            gv = fmaf(n_i[k].z, m, -u_i[k].z); gh = c_i[k].w - c_i[k].y;
            a  = fsqrt_ap(fmaf(gv, gv, fmaf(gh, gh, EPS)));
            gv = fmaf(n_t[k].z, m, -u_t[k].z); gh = c_t[k].w - c_t[k].y;
            b  = fsqrt_ap(fmaf(gv, gv, fmaf(gh, gh, EPS)));
            sum += fabsf(a - b);

            gv = fmaf(n_i[k].w, m, -u_i[k].w); gh = rci - c_i[k].z;
            a  = fsqrt_ap(fmaf(gv, gv, fmaf(gh, gh, EPS)));
            gv = fmaf(n_t[k].w, m, -u_t[k].w); gh = rct - c_t[k].z;
            b  = fsqrt_ap(fmaf(gv, gv, fmaf(gh, gh, EPS)));
            sum += fabsf(a - b);
        }

        pi += WW; pt += WW; pe_i += WW; pe_t += WW;
    };

    int rg = ws;
    for (; rg + 3 <= we; rg += 3) {
        step(Ai, Bi, Ci, At, Bt, Ct, eAi, eBi, eCi, eAt, eBt, eCt, rg);
        step(Bi, Ci, Ai, Bt, Ct, At, eBi, eCi, eAi, eBt, eCt, eAt, rg + 1);
        step(Ci, Ai, Bi, Ct, At, Bt, eCi, eAi, eBi, eCt, eAt, eBt, rg + 2);
    }
    if (rg < we) { step(Ai, Bi, Ci, At, Bt, Ct, eAi, eBi, eCi, eAt, eBt, eCt, rg); ++rg; }
    if (rg < we) { step(Bi, Ci, Ai, Bt, Ct, At, eBi, eCi, eAi, eBt, eCt, eAt, rg); ++rg; }

    // ---------- block reduction + last-block-ticket finisher ----------
    #pragma unroll
    for (int o = 16; o > 0; o >>= 1)
        sum += __shfl_down_sync(0xffffffffu, sum, o);

    __shared__ float wsum[TPB / 32];
    __shared__ bool is_last;
    if (lane == 0) wsum[wid] = sum;
    __syncthreads();

    if (t == 0) {
        float ssum = wsum[0] + wsum[1] + wsum[2] + wsum[3];
        g_partials[blockIdx.x] = ssum;
        __threadfence();                               // partial visible before ticket
        unsigned done = atomicAdd(&g_ticket, 1u);
        is_last = (done == (unsigned)(NBLK - 1));
    }
    __syncthreads();

    if (is_last) {
        const volatile float* vp = (const volatile float*)g_partials;
        float ssum = 0.f;
        for (int i = t; i < NBLK; i += TPB)
            ssum += vp[i];

        #pragma unroll
        for (int o = 16; o > 0; o >>= 1)
            ssum += __shfl_down_sync(0xffffffffu, ssum, o);

        if (lane == 0) wsum[wid] = ssum;
        __syncthreads();
        if (t == 0) {
            out[0] = (wsum[0] + wsum[1] + wsum[2] + wsum[3]) * inv_n;
            g_ticket = 0;                              // reset for next graph replay
        }
    }
}

extern "C" void kernel_launch(void* const* d_in, const int* in_sizes, int n_in,
                              void* d_out, int out_size) {
    const float* in = (const float*)d_in[0];
    const float* tg = (const float*)d_in[1];
    float* out = (float*)d_out;

    const int total = in_sizes[0];                 // 32*3*512*512
    const int total_rows = total / WW;             // 49152

    grad_loss_kernel<<<NBLK, TPB>>>(in, tg, out, total_rows, 1.0f / (float)total);
}

// round 14
// speedup vs baseline: 1.2597x; 1.1144x over previous
#include <cuda_runtime.h>

#define HH 512
#define WW 512
#define TPB 128           // 4 warps per block; each WARP owns full 512-col rows
#define NBLK 608          // 152 SMs * 4 blocks/SM (one wave at the reg-limited cap)
#define EPS 1e-6f

// scratch for per-block partial sums + completion ticket (no cudaMalloc allowed)
__device__ float g_partials[NBLK];
__device__ unsigned int g_ticket;   // zero-init; last block resets it to 0

__device__ __forceinline__ float4 ld4(const float* __restrict__ p) {
    return *reinterpret_cast<const float4*>(p);
}

// single-MUFU approximate sqrt (max rel err ~1e-7, far below 1e-3 tolerance)
__device__ __forceinline__ float fsqrt_ap(float x) {
    float r;
    asm("sqrt.approx.f32 %0, %1;" : "=f"(r) : "f"(x));
    return r;
}

// L2 prefetch: no destination register, no scoreboard — pure hint
__device__ __forceinline__ void pf_l2(const float* p) {
    asm volatile("prefetch.global.L2 [%0];" :: "l"(p));
}

__global__ __launch_bounds__(TPB, 4)   // up to 128 regs; 4 blocks/SM
void grad_loss_kernel(const float* __restrict__ in, const float* __restrict__ tg,
                      float* __restrict__ out, int total_rows, float inv_n) {
    const int t     = threadIdx.x;
    const int lane  = t & 31;
    const int wid   = t >> 5;
    const int gw    = blockIdx.x * 4 + wid;       // global warp id
    const int laneL = (lane + 31) & 31;           // rotate: lane reads lane-1 (wrap)
    const int laneR = (lane + 1) & 31;            // rotate: lane reads lane+1 (wrap)

    // contiguous row slice per warp over the flattened row space
    const int nw   = NBLK * 4;
    const int base = total_rows / nw;
    const int rem  = total_rows % nw;
    const int ws   = gw * base + min(gw, rem);
    const int we   = ws + base + (gw < rem ? 1 : 0);

    // lane covers cols {k*128 + lane*4 .. +4}, k=0..3 (512B coalesced chunk loads)
    const float* pi = in + (size_t)ws * WW + lane * 4;
    const float* pt = tg + (size_t)ws * WW + lane * 4;

    const float4 z4 = make_float4(0.f, 0.f, 0.f, 0.f);
    // 4 accumulators: break the serial FADD dependency chain
    float sum0 = 0.f, sum1 = 0.f, sum2 = 0.f, sum3 = 0.f;

    // 3 rotating row buffers per array, 4 chunks each: roles (u, c, n)
    float4 Xi[4], Yi[4], Zi[4], Xt[4], Yt[4], Zt[4];

    #pragma unroll
    for (int k = 0; k < 4; ++k) {
        Xi[k] = (ws > 0) ? ld4(pi - WW + k * 128) : z4;   // row ws-1
        Xt[k] = (ws > 0) ? ld4(pt - WW + k * 128) : z4;
        Yi[k] = ld4(pi + k * 128);                        // row ws
        Yt[k] = ld4(pt + k * 128);
    }

    // one step: L2-prefetch row rg+2, compute row rg from (u, c, n)
    auto step = [&](float4 (&u_i)[4], float4 (&c_i)[4], float4 (&n_i)[4],
                    float4 (&u_t)[4], float4 (&c_t)[4], float4 (&n_t)[4], int rg) {
        const int r = rg & (HH - 1);
        if (r != HH - 1) {                    // common path: load next row
            #pragma unroll
            for (int k = 0; k < 4; ++k) {
                n_i[k] = ld4(pi + WW + k * 128);
                n_t[k] = ld4(pt + WW + k * 128);
            }
        } else {                              // plane-last row: zero-pad below
            #pragma unroll
            for (int k = 0; k < 4; ++k) { n_i[k] = z4; n_t[k] = z4; }
        }
        if (r == 0) {                         // plane-first row: zero-pad above
            #pragma unroll
            for (int k = 0; k < 4; ++k) { u_i[k] = z4; u_t[k] = z4; }
        }

        // L2 prefetch of row rg+2 (zero registers, no scoreboard); by the time
        // the next step's LDGs issue, these lines are in L2 (~250 vs ~577 cyc)
        if (rg + 2 < total_rows) {
            #pragma unroll
            for (int k = 0; k < 4; ++k) {
                pf_l2(pi + 2 * WW + k * 128);
                pf_l2(pt + 2 * WW + k * 128);
            }
        }

        #pragma unroll
        for (int k = 0; k < 4; ++k) {
            // horizontal neighbors: rotate-shuffles, register-sourced, no loads
            float xl_i = (lane == 31) ? (k > 0 ? c_i[k - 1].w : 0.f) : c_i[k].w;
            float xl_t = (lane == 31) ? (k > 0 ? c_t[k - 1].w : 0.f) : c_t[k].w;
            const float lci = __shfl_sync(0xffffffffu, xl_i, laneL);
            const float lct = __shfl_sync(0xffffffffu, xl_t, laneL);
            float xr_i = (lane == 0) ? (k < 3 ? c_i[k + 1].x : 0.f) : c_i[k].x;
            float xr_t = (lane == 0) ? (k < 3 ? c_t[k + 1].x : 0.f) : c_t[k].x;
            const float rci = __shfl_sync(0xffffffffu, xr_i, laneR);
            const float rct = __shfl_sync(0xffffffffu, xr_t, laneR);

            float gv, gh, a, b;

            gv = n_i[k].x - u_i[k].x; gh = c_i[k].y - lci;
            a  = fsqrt_ap(fmaf(gv, gv, fmaf(gh, gh, EPS)));
            gv = n_t[k].x - u_t[k].x; gh = c_t[k].y - lct;
            b  = fsqrt_ap(fmaf(gv, gv, fmaf(gh, gh, EPS)));
            sum0 += fabsf(a - b);

            gv = n_i[k].y - u_i[k].y; gh = c_i[k].z - c_i[k].x;
            a  = fsqrt_ap(fmaf(gv, gv, fmaf(gh, gh, EPS)));
            gv = n_t[k].y - u_t[k].y; gh = c_t[k].z - c_t[k].x;
            b  = fsqrt_ap(fmaf(gv, gv, fmaf(gh, gh, EPS)));
            sum1 += fabsf(a - b);

            gv = n_i[k].z - u_i[k].z; gh = c_i[k].w - c_i[k].y;
            a  = fsqrt_ap(fmaf(gv, gv, fmaf(gh, gh, EPS)));
            gv = n_t[k].z - u_t[k].z; gh = c_t[k].w - c_t[k].y;
            b  = fsqrt_ap(fmaf(gv, gv, fmaf(gh, gh, EPS)));
            sum2 += fabsf(a - b);

            gv = n_i[k].w - u_i[k].w; gh = rci - c_i[k].z;
            a  = fsqrt_ap(fmaf(gv, gv, fmaf(gh, gh, EPS)));
            gv = n_t[k].w - u_t[k].w; gh = rct - c_t[k].z;
            b  = fsqrt_ap(fmaf(gv, gv, fmaf(gh, gh, EPS)));
            sum3 += fabsf(a - b);
        }

        // plane-last row zeroed n, but next iteration needs c = real row rg+1:
        // rare uniform reload (once per 512 rows; L2 hit)
        if (r == HH - 1 && rg + 1 < total_rows) {
            #pragma unroll
            for (int k = 0; k < 4; ++k) {
                n_i[k] = ld4(pi + WW + k * 128);
                n_t[k] = ld4(pt + WW + k * 128);
            }
        }

        pi += WW; pt += WW;
    };

    int rg = ws;
    for (; rg + 3 <= we; rg += 3) {
        step(Xi, Yi, Zi, Xt, Yt, Zt, rg);
        step(Yi, Zi, Xi, Yt, Zt, Xt, rg + 1);
        step(Zi, Xi, Yi, Zt, Xt, Yt, rg + 2);
    }
    if (rg < we) { step(Xi, Yi, Zi, Xt, Yt, Zt, rg); ++rg; }
    if (rg < we) { step(Yi, Zi, Xi, Yt, Zt, Xt, rg); ++rg; }

    float sum = (sum0 + sum1) + (sum2 + sum3);

    // ---------- block reduction + last-block-ticket finisher ----------
    #pragma unroll
    for (int o = 16; o > 0; o >>= 1)
        sum += __shfl_down_sync(0xffffffffu, sum, o);

    __shared__ float wsum[TPB / 32];
    __shared__ bool is_last;
    if (lane == 0) wsum[wid] = sum;
    __syncthreads();

    if (t == 0) {
        float s = wsum[0] + wsum[1] + wsum[2] + wsum[3];
        g_partials[blockIdx.x] = s;
        __threadfence();                               // partial visible before ticket
        unsigned done = atomicAdd(&g_ticket, 1u);
        is_last = (done == (unsigned)(NBLK - 1));
    }
    __syncthreads();

    if (is_last) {
        const volatile float* vp = (const volatile float*)g_partials;
        float s = 0.f;
        for (int i = t; i < NBLK; i += TPB)
            s += vp[i];

        #pragma unroll
        for (int o = 16; o > 0; o >>= 1)
            s += __shfl_down_sync(0xffffffffu, s, o);

        if (lane == 0) wsum[wid] = s;
        __syncthreads();
        if (t == 0) {
            out[0] = (wsum[0] + wsum[1] + wsum[2] + wsum[3]) * inv_n;
            g_ticket = 0;                              // reset for next graph replay
        }
    }
}

extern "C" void kernel_launch(void* const* d_in, const int* in_sizes, int n_in,
                              void* d_out, int out_size) {
    const float* in = (const float*)d_in[0];
    const float* tg = (const float*)d_in[1];
    float* out = (float*)d_out;

    const int total = in_sizes[0];                 // 32*3*512*512
    const int total_rows = total / WW;             // 49152

    grad_loss_kernel<<<NBLK, TPB>>>(in, tg, out, total_rows, 1.0f / (float)total);
}

// round 15
// speedup vs baseline: 1.2711x; 1.0090x over previous
#include <cuda_runtime.h>

#define HH 512
#define WW 512
#define TPB 128           // 4 warps per block; each WARP owns full 512-col rows
#define NBLK 608          // 152 SMs * 4 blocks/SM (one wave at the reg-limited cap)
#define EPS 1e-6f

// scratch for per-block partial sums + completion ticket (no cudaMalloc allowed)
__device__ float g_partials[NBLK];
__device__ unsigned int g_ticket;   // zero-init; last block resets it to 0

__device__ __forceinline__ float4 ld4(const float* __restrict__ p) {
    return *reinterpret_cast<const float4*>(p);
}

// single-MUFU approximate sqrt (max rel err ~1e-7, far below 1e-3 tolerance)
__device__ __forceinline__ float fsqrt_ap(float x) {
    float r;
    asm("sqrt.approx.f32 %0, %1;" : "=f"(r) : "f"(x));
    return r;
}

// L1 prefetch: no destination register, no scoreboard — pure hint.
// Issued one full row-step (~2k cyc) before the LDG consumes the line,
// so the DRAM->L1 journey (~577 cyc) completes entirely in the shadow.
__device__ __forceinline__ void pf_l1(const float* p) {
    asm volatile("prefetch.global.L1 [%0];" :: "l"(p));
}

__global__ __launch_bounds__(TPB, 4)   // up to 128 regs; 4 blocks/SM
void grad_loss_kernel(const float* __restrict__ in, const float* __restrict__ tg,
                      float* __restrict__ out, int total_rows, float inv_n) {
    const int t     = threadIdx.x;
    const int lane  = t & 31;
    const int wid   = t >> 5;
    const int gw    = blockIdx.x * 4 + wid;       // global warp id
    const int laneL = (lane + 31) & 31;           // rotate: lane reads lane-1 (wrap)
    const int laneR = (lane + 1) & 31;            // rotate: lane reads lane+1 (wrap)

    // contiguous row slice per warp over the flattened row space
    const int nw   = NBLK * 4;
    const int base = total_rows / nw;
    const int rem  = total_rows % nw;
    const int ws   = gw * base + min(gw, rem);
    const int we   = ws + base + (gw < rem ? 1 : 0);

    // lane covers cols {k*128 + lane*4 .. +4}, k=0..3 (512B coalesced chunk loads)
    const float* pi = in + (size_t)ws * WW + lane * 4;
    const float* pt = tg + (size_t)ws * WW + lane * 4;

    const float4 z4 = make_float4(0.f, 0.f, 0.f, 0.f);
    // 4 accumulators: break the serial FADD dependency chain
    float sum0 = 0.f, sum1 = 0.f, sum2 = 0.f, sum3 = 0.f;

    // 3 rotating row buffers per array, 4 chunks each: roles (u, c, n)
    float4 Xi[4], Yi[4], Zi[4], Xt[4], Yt[4], Zt[4];

    #pragma unroll
    for (int k = 0; k < 4; ++k) {
        Xi[k] = (ws > 0) ? ld4(pi - WW + k * 128) : z4;   // row ws-1
        Xt[k] = (ws > 0) ? ld4(pt - WW + k * 128) : z4;
        Yi[k] = ld4(pi + k * 128);                        // row ws
        Yt[k] = ld4(pt + k * 128);
    }

    // one step: L1-prefetch row rg+2, compute row rg from (u, c, n)
    auto step = [&](float4 (&u_i)[4], float4 (&c_i)[4], float4 (&n_i)[4],
                    float4 (&u_t)[4], float4 (&c_t)[4], float4 (&n_t)[4], int rg) {
        const int r = rg & (HH - 1);
        if (r != HH - 1) {                    // common path: load next row (L1 hit)
            #pragma unroll
            for (int k = 0; k < 4; ++k) {
                n_i[k] = ld4(pi + WW + k * 128);
                n_t[k] = ld4(pt + WW + k * 128);
            }
        } else {                              // plane-last row: zero-pad below
            #pragma unroll
            for (int k = 0; k < 4; ++k) { n_i[k] = z4; n_t[k] = z4; }
        }
        if (r == 0) {                         // plane-first row: zero-pad above
            #pragma unroll
            for (int k = 0; k < 4; ++k) { u_i[k] = z4; u_t[k] = z4; }
        }

        // L1 prefetch of row rg+2 (zero registers, no scoreboard); consumed by
        // the NEXT step's LDGs — a full row-step of slack covers DRAM latency
        if (rg + 2 < total_rows) {
            #pragma unroll
            for (int k = 0; k < 4; ++k) {
                pf_l1(pi + 2 * WW + k * 128);
                pf_l1(pt + 2 * WW + k * 128);
            }
        }

        #pragma unroll
        for (int k = 0; k < 4; ++k) {
            // horizontal neighbors: rotate-shuffles, register-sourced, no loads
            float xl_i = (lane == 31) ? (k > 0 ? c_i[k - 1].w : 0.f) : c_i[k].w;
            float xl_t = (lane == 31) ? (k > 0 ? c_t[k - 1].w : 0.f) : c_t[k].w;
            const float lci = __shfl_sync(0xffffffffu, xl_i, laneL);
            const float lct = __shfl_sync(0xffffffffu, xl_t, laneL);
            float xr_i = (lane == 0) ? (k < 3 ? c_i[k + 1].x : 0.f) : c_i[k].x;
            float xr_t = (lane == 0) ? (k < 3 ? c_t[k + 1].x : 0.f) : c_t[k].x;
            const float rci = __shfl_sync(0xffffffffu, xr_i, laneR);
            const float rct = __shfl_sync(0xffffffffu, xr_t, laneR);

            float gv, gh, a, b;

            gv = n_i[k].x - u_i[k].x; gh = c_i[k].y - lci;
            a  = fsqrt_ap(fmaf(gv, gv, fmaf(gh, gh, EPS)));
            gv = n_t[k].x - u_t[k].x; gh = c_t[k].y - lct;
            b  = fsqrt_ap(fmaf(gv, gv, fmaf(gh, gh, EPS)));
            sum0 += fabsf(a - b);

            gv = n_i[k].y - u_i[k].y; gh = c_i[k].z - c_i[k].x;
            a  = fsqrt_ap(fmaf(gv, gv, fmaf(gh, gh, EPS)));
            gv = n_t[k].y - u_t[k].y; gh = c_t[k].z - c_t[k].x;
            b  = fsqrt_ap(fmaf(gv, gv, fmaf(gh, gh, EPS)));
            sum1 += fabsf(a - b);

            gv = n_i[k].z - u_i[k].z; gh = c_i[k].w - c_i[k].y;
            a  = fsqrt_ap(fmaf(gv, gv, fmaf(gh, gh, EPS)));
            gv = n_t[k].z - u_t[k].z; gh = c_t[k].w - c_t[k].y;
            b  = fsqrt_ap(fmaf(gv, gv, fmaf(gh, gh, EPS)));
            sum2 += fabsf(a - b);

            gv = n_i[k].w - u_i[k].w; gh = rci - c_i[k].z;
            a  = fsqrt_ap(fmaf(gv, gv, fmaf(gh, gh, EPS)));
            gv = n_t[k].w - u_t[k].w; gh = rct - c_t[k].z;
            b  = fsqrt_ap(fmaf(gv, gv, fmaf(gh, gh, EPS)));
            sum3 += fabsf(a - b);
        }

        // plane-last row zeroed n, but next iteration needs c = real row rg+1:
        // rare uniform reload (once per 512 rows; L1/L2 hit)
        if (r == HH - 1 && rg + 1 < total_rows) {
            #pragma unroll
            for (int k = 0; k < 4; ++k) {
                n_i[k] = ld4(pi + WW + k * 128);
                n_t[k] = ld4(pt + WW + k * 128);
            }
        }

        pi += WW; pt += WW;
    };

    int rg = ws;
    for (; rg + 3 <= we; rg += 3) {
        step(Xi, Yi, Zi, Xt, Yt, Zt, rg);
        step(Yi, Zi, Xi, Yt, Zt, Xt, rg + 1);
        step(Zi, Xi, Yi, Zt, Xt, Yt, rg + 2);
    }
    if (rg < we) { step(Xi, Yi, Zi, Xt, Yt, Zt, rg); ++rg; }
    if (rg < we) { step(Yi, Zi, Xi, Yt, Zt, Xt, rg); ++rg; }

    float sum = (sum0 + sum1) + (sum2 + sum3);

    // ---------- block reduction + last-block-ticket finisher ----------
    #pragma unroll
    for (int o = 16; o > 0; o >>= 1)
        sum += __shfl_down_sync(0xffffffffu, sum, o);

    __shared__ float wsum[TPB / 32];
    __shared__ bool is_last;
    if (lane == 0) wsum[wid] = sum;
    __syncthreads();

    if (t == 0) {
        float s = wsum[0] + wsum[1] + wsum[2] + wsum[3];
        g_partials[blockIdx.x] = s;
        __threadfence();                               // partial visible before ticket
        unsigned done = atomicAdd(&g_ticket, 1u);
        is_last = (done == (unsigned)(NBLK - 1));
    }
    __syncthreads();

    if (is_last) {
        const volatile float* vp = (const volatile float*)g_partials;
        float s = 0.f;
        for (int i = t; i < NBLK; i += TPB)
            s += vp[i];

        #pragma unroll
        for (int o = 16; o > 0; o >>= 1)
            s += __shfl_down_sync(0xffffffffu, s, o);

        if (lane == 0) wsum[wid] = s;
        __syncthreads();
        if (t == 0) {
            out[0] = (wsum[0] + wsum[1] + wsum[2] + wsum[3]) * inv_n;
            g_ticket = 0;                              // reset for next graph replay
        }
    }
}

extern "C" void kernel_launch(void* const* d_in, const int* in_sizes, int n_in,
                              void* d_out, int out_size) {
    const float* in = (const float*)d_in[0];
    const float* tg = (const float*)d_in[1];
    float* out = (float*)d_out;

    const int total = in_sizes[0];                 // 32*3*512*512
    const int total_rows = total / WW;             // 49152

    grad_loss_kernel<<<NBLK, TPB>>>(in, tg, out, total_rows, 1.0f / (float)total);
}